// round 2
// baseline (speedup 1.0000x reference)
#include <cuda_runtime.h>

#define DIM 496

// pair index of (x,y), x<y, in itertools.combinations(range(32),2) order
__device__ __forceinline__ int pidx(int x, int y) {
    return x * 31 - ((x * (x - 1)) >> 1) + (y - x - 1);
}

// Decode orbit o in [0,124): 4 member basis indices m[0..3] laid out as
// m[alpha*2+beta]; outer gate gO acts on alpha, inner gate gI on beta.
// Gate id 15 == identity (cos=1, sin=0).
__device__ __forceinline__ void decode_orbit(int o, int m[4], int& gO, int& gI) {
    if (o < 105) {                       // cross-block (g<h<15): R_g (x) R_h
        int g = 0, rem = o;
        while (rem >= 14 - g) { rem -= 14 - g; ++g; }
        int h = g + 1 + rem;
        gO = g; gI = h;
        m[0] = pidx(2 * g,     2 * h);
        m[1] = pidx(2 * g,     2 * h + 1);
        m[2] = pidx(2 * g + 1, 2 * h);
        m[3] = pidx(2 * g + 1, 2 * h + 1);
    } else if (o < 120) {                // block g paired with qubits 30/31: R_g (x) I
        int g = o - 105;
        gO = g; gI = 15;
        m[0] = pidx(2 * g,     30);
        m[1] = pidx(2 * g,     31);
        m[2] = pidx(2 * g + 1, 30);
        m[3] = pidx(2 * g + 1, 31);
    } else {                             // 16 identity singletons grouped 4-at-a-time
        int j = o - 120;
        gO = 15; gI = 15;
#pragma unroll
        for (int k = 0; k < 4; ++k) {
            int q = 4 * j + k;
            m[k] = pidx(2 * q, 2 * q + 1);
        }
    }
}

// Block: one row-orbit (4 rows) x 2 batches. 256 threads:
//   half = tid>>7 selects batch, lane = tid&127 is the float4 column chunk /
//   column-orbit id (active for lane < 124).
__global__ __launch_bounds__(256) void rbs_density_kernel(
    const float* __restrict__ rho, const float* __restrict__ angles,
    float* __restrict__ out)
{
    __shared__ float S[2][4][DIM];       // 15.9 KB
    __shared__ float cs[16], sn[16];

    const int tid  = threadIdx.x;
    const int lane = tid & 127;
    const int half = tid >> 7;
    const int ro   = blockIdx.x;                 // row orbit 0..123
    const int b    = blockIdx.y * 2 + half;      // batch 0..7

    if (tid < 16) {
        if (tid < 15) {
            float s, c;
            sincosf(angles[tid], &s, &c);
            cs[tid] = c; sn[tid] = s;
        } else {
            cs[15] = 1.0f; sn[15] = 0.0f;
        }
    }

    int rm[4], rgO, rgI;
    decode_orbit(ro, rm, rgO, rgI);

    const size_t boff = (size_t)b * DIM * DIM;

    // Phase 1: load 4 rows (float4-coalesced) into registers, apply the ROW
    // rotation in registers, write rotated rows to smem. (cs/sn written by
    // warp 0 before its first loads return; all consumers sync below anyway —
    // but we need cs/sn *here*, so guard with a sync first.)
    __syncthreads();

    float4 v[4];
    if (lane < 124) {
#pragma unroll
        for (int i = 0; i < 4; ++i)
            v[i] = ((const float4*)(rho + boff + (size_t)rm[i] * DIM))[lane];

        const float ci = cs[rgI], si = sn[rgI];
        const float co = cs[rgO], so = sn[rgO];
#pragma unroll
        for (int k = 0; k < 4; ++k) {    // per float4 component
            float v0 = ((float*)&v[0])[k], v1 = ((float*)&v[1])[k];
            float v2 = ((float*)&v[2])[k], v3 = ((float*)&v[3])[k];
            // inner rotation on beta: pairs (0,1),(2,3)
            float t0 = ci * v0 + si * v1, t1 = ci * v1 - si * v0;
            float t2 = ci * v2 + si * v3, t3 = ci * v3 - si * v2;
            // outer rotation on alpha: pairs (0,2),(1,3)
            ((float*)&v[0])[k] = co * t0 + so * t2;
            ((float*)&v[2])[k] = co * t2 - so * t0;
            ((float*)&v[1])[k] = co * t1 + so * t3;
            ((float*)&v[3])[k] = co * t3 - so * t1;
        }
#pragma unroll
        for (int i = 0; i < 4; ++i)
            ((float4*)S[half][i])[lane] = v[i];
    }
    __syncthreads();

    // Phase 2: COLUMN rotation in smem. Thread `lane` owns column-orbit `lane`
    // (disjoint 4-column sets -> in-place safe), for its batch half.
    if (lane < 124) {
        int cm[4], cgO, cgI;
        decode_orbit(lane, cm, cgO, cgI);
        const float ci = cs[cgI], si = sn[cgI];
        const float co = cs[cgO], so = sn[cgO];
#pragma unroll
        for (int i = 0; i < 4; ++i) {
            float w0 = S[half][i][cm[0]], w1 = S[half][i][cm[1]];
            float w2 = S[half][i][cm[2]], w3 = S[half][i][cm[3]];
            float t0 = ci * w0 + si * w1, t1 = ci * w1 - si * w0;
            float t2 = ci * w2 + si * w3, t3 = ci * w3 - si * w2;
            S[half][i][cm[0]] = co * t0 + so * t2;
            S[half][i][cm[2]] = co * t2 - so * t0;
            S[half][i][cm[1]] = co * t1 + so * t3;
            S[half][i][cm[3]] = co * t3 - so * t1;
        }
    }
    __syncthreads();

    // Phase 3: coalesced float4 store of the 4 transformed rows.
    if (lane < 124) {
#pragma unroll
        for (int i = 0; i < 4; ++i)
            ((float4*)(out + boff + (size_t)rm[i] * DIM))[lane] =
                ((const float4*)S[half][i])[lane];
    }
}

extern "C" void kernel_launch(void* const* d_in, const int* in_sizes, int n_in,
                              void* d_out, int out_size) {
    const float* rho = (const float*)d_in[0];
    const float* ang = (const float*)d_in[1];
    if (n_in >= 2 && in_sizes[0] == 15) {   // defensive input-order swap
        rho = (const float*)d_in[1];
        ang = (const float*)d_in[0];
    }
    dim3 grid(124, 4);
    rbs_density_kernel<<<grid, 256>>>(rho, ang, (float*)d_out);
}